// round 6
// baseline (speedup 1.0000x reference)
#include <cuda_runtime.h>
#include <cstdint>

// Problem constants
#define N_ENS  4
#define N_IN   16384
#define N_OUT  4096
#define CIN    16
#define COUT   16
#define KS     2048                 // K-slab staged in SMEM
#define NSLAB  (N_IN / KS)          // 8
#define MAIN_BLOCKS (N_OUT / 32)    // 128 blocks, 32 rows each

// Scratch: xw transposed to planes [n][g2][i] as float2 (pair over g).
// 4 * 8 * 16384 * 8 B = 4 MB. (__device__ global: allocation-free.)
__device__ float2 g_xwT[N_ENS * 8 * N_IN];

// ---------------------------------------------------------------------------
// Packed fp32x2 FMA (Blackwell FFMA2) — only reachable via PTX.
// ---------------------------------------------------------------------------
union F2U { float2 f; unsigned long long u; };

__device__ __forceinline__ float2 ffma2(float2 a, float2 b, float2 c) {
    F2U A, B, C, D;
    A.f = a; B.f = b; C.f = c;
    asm("fma.rn.f32x2 %0, %1, %2, %3;"
        : "=l"(D.u) : "l"(A.u), "l"(B.u), "l"(C.u));
    return D.f;
}

// ---------------------------------------------------------------------------
// Kernel 0: xw[n][i][g] = 0.25 * sum_f x[i][f] * W[n][f][g], stored as
// g_xwT[n][g2][i] = (xw[..][2g2], xw[..][2g2+1]).  Tiny (~5 us).
// ---------------------------------------------------------------------------
__global__ void precompute_xw(const float* __restrict__ x,
                              const float* __restrict__ Ws) {
    __shared__ float sW[CIN * COUT];
    const int n = blockIdx.y;
    sW[threadIdx.x] = Ws[n * (CIN * COUT) + threadIdx.x];
    __syncthreads();

    const int i = blockIdx.x * 256 + threadIdx.x;

    float xf[16];
    const float4* xv = reinterpret_cast<const float4*>(x + (size_t)i * CIN);
#pragma unroll
    for (int q = 0; q < 4; ++q)
        reinterpret_cast<float4*>(xf)[q] = xv[q];

    float y[16];
#pragma unroll
    for (int g = 0; g < 16; ++g) y[g] = 0.f;
#pragma unroll
    for (int f = 0; f < 16; ++f)
#pragma unroll
        for (int g = 0; g < 16; ++g)
            y[g] += xf[f] * sW[f * 16 + g];

#pragma unroll
    for (int g2 = 0; g2 < 8; ++g2)
        g_xwT[(n * 8 + g2) * N_IN + i] =
            make_float2(0.25f * y[2 * g2], 0.25f * y[2 * g2 + 1]);
}

// ---------------------------------------------------------------------------
// Main kernel: block owns 32 output rows (8 warps x 4 rows), loops over all
// 4 ensemble members and 8 K-slabs. Lanes split K (coalesced A stream);
// xw slab in SMEM as 8 planes [g2][KS] float2 (conflict-free LDS.64).
// Accumulators live in registers, warp-reduced at the end; lane 0 writes.
// ---------------------------------------------------------------------------
extern __shared__ float2 s_xw[];   // 8 * KS float2 = 128 KB

__global__ __launch_bounds__(256, 1)
void mfgl_main(const float* __restrict__ A,
               const float* __restrict__ bs,
               float* __restrict__ out) {
    const int tid  = threadIdx.x;
    const int lane = tid & 31;
    const int wid  = tid >> 5;
    const int row_base = blockIdx.x * 32 + wid * 4;

    float2 acc[4][8];
#pragma unroll
    for (int r = 0; r < 4; ++r)
#pragma unroll
        for (int g = 0; g < 8; ++g)
            acc[r][g] = make_float2(0.f, 0.f);

    for (int n = 0; n < N_ENS; ++n) {
        const float2* __restrict__ xw_n = g_xwT + (size_t)n * 8 * N_IN;

        for (int s = 0; s < NSLAB; ++s) {
            __syncthreads();  // previous slab fully consumed
            const int k0 = s * KS;
            // Cooperative slab load: 8*KS float2, coalesced within each plane.
#pragma unroll 8
            for (int j = tid; j < 8 * KS; j += 256) {
                const int g2 = j >> 11;          // j / KS  (KS = 2048)
                const int il = j & (KS - 1);
                s_xw[j] = xw_n[g2 * N_IN + k0 + il];
            }
            __syncthreads();

            const size_t base = ((size_t)(n * N_OUT + row_base)) * N_IN + k0 + lane;
            const float* __restrict__ a0 = A + base;
            const float* __restrict__ a1 = a0 + N_IN;
            const float* __restrict__ a2 = a1 + N_IN;
            const float* __restrict__ a3 = a2 + N_IN;

#pragma unroll 4
            for (int t = 0; t < KS / 32; ++t) {
                const int o = t * 32;
                const float v0 = a0[o];
                const float v1 = a1[o];
                const float v2 = a2[o];
                const float v3 = a3[o];
                const float2 p0 = make_float2(v0, v0);
                const float2 p1 = make_float2(v1, v1);
                const float2 p2 = make_float2(v2, v2);
                const float2 p3 = make_float2(v3, v3);
                const float2* __restrict__ xr = s_xw + o + lane;
#pragma unroll
                for (int g2 = 0; g2 < 8; ++g2) {
                    const float2 w = xr[g2 * KS];
                    acc[0][g2] = ffma2(p0, w, acc[0][g2]);
                    acc[1][g2] = ffma2(p1, w, acc[1][g2]);
                    acc[2][g2] = ffma2(p2, w, acc[2][g2]);
                    acc[3][g2] = ffma2(p3, w, acc[3][g2]);
                }
            }
        }
    }

    // Warp-level reduction across the K split (butterfly; all lanes end equal).
#pragma unroll
    for (int r = 0; r < 4; ++r)
#pragma unroll
        for (int g = 0; g < 8; ++g) {
            float xx = acc[r][g].x;
            float yy = acc[r][g].y;
#pragma unroll
            for (int off = 16; off > 0; off >>= 1) {
                xx += __shfl_xor_sync(0xffffffffu, xx, off);
                yy += __shfl_xor_sync(0xffffffffu, yy, off);
            }
            acc[r][g] = make_float2(xx, yy);
        }

    if (lane == 0) {
        float2* out2 = reinterpret_cast<float2*>(out);
#pragma unroll
        for (int r = 0; r < 4; ++r) {
            const int o = row_base + r;
#pragma unroll
            for (int g2 = 0; g2 < 8; ++g2) {
                const int g = 2 * g2;
                const float bx = 0.25f * (bs[g]     + bs[16 + g]     +
                                          bs[32 + g]     + bs[48 + g]);
                const float by = 0.25f * (bs[g + 1] + bs[16 + g + 1] +
                                          bs[32 + g + 1] + bs[48 + g + 1]);
                out2[(size_t)o * 8 + g2] =
                    make_float2(acc[r][g2].x + bx, acc[r][g2].y + by);
            }
        }
    }
}

// ---------------------------------------------------------------------------
// Launch: inputs in metadata order: x, As, Ws, bs. Output fp32 [4096,16].
// ---------------------------------------------------------------------------
extern "C" void kernel_launch(void* const* d_in, const int* in_sizes, int n_in,
                              void* d_out, int out_size) {
    const float* x  = (const float*)d_in[0];
    const float* As = (const float*)d_in[1];
    const float* Ws = (const float*)d_in[2];
    const float* bs = (const float*)d_in[3];
    float* out = (float*)d_out;

    precompute_xw<<<dim3(N_IN / 256, N_ENS), 256>>>(x, Ws);

    const int smem_bytes = 8 * KS * (int)sizeof(float2);  // 131072
    cudaFuncSetAttribute(mfgl_main,
                         cudaFuncAttributeMaxDynamicSharedMemorySize,
                         smem_bytes);
    mfgl_main<<<MAIN_BLOCKS, 256, smem_bytes>>>(As, bs, out);
}

// round 7
// speedup vs baseline: 1.0145x; 1.0145x over previous
#include <cuda_runtime.h>
#include <cstdint>

// Problem constants
#define N_ENS  4
#define N_IN   16384
#define N_OUT  4096
#define CIN    16
#define COUT   16
#define KS     2048                 // K-slab staged in SMEM
#define NSLAB  (N_IN / KS)          // 8
#define MAIN_BLOCKS (N_OUT / 32)    // 128 blocks, 32 rows each

// Scratch: xw transposed to planes [n][g2][i] as float2 (pair over g).
// 4 * 8 * 16384 * 8 B = 4 MB. (__device__ global: allocation-free.)
__device__ float2 g_xwT[N_ENS * 8 * N_IN];

// ---------------------------------------------------------------------------
// Packed fp32x2 FMA (Blackwell FFMA2) — only reachable via PTX.
// ---------------------------------------------------------------------------
union F2U { float2 f; unsigned long long u; };

__device__ __forceinline__ float2 ffma2(float2 a, float2 b, float2 c) {
    F2U A, B, C, D;
    A.f = a; B.f = b; C.f = c;
    asm("fma.rn.f32x2 %0, %1, %2, %3;"
        : "=l"(D.u) : "l"(A.u), "l"(B.u), "l"(C.u));
    return D.f;
}

// ---------------------------------------------------------------------------
// Kernel 0: xw[n][i][g] = 0.25 * sum_f x[i][f] * W[n][f][g], stored as
// g_xwT[n][g2][i] = (xw[..][2g2], xw[..][2g2+1]).  Tiny (~5 us).
// ---------------------------------------------------------------------------
__global__ void precompute_xw(const float* __restrict__ x,
                              const float* __restrict__ Ws) {
    __shared__ float sW[CIN * COUT];
    const int n = blockIdx.y;
    sW[threadIdx.x] = Ws[n * (CIN * COUT) + threadIdx.x];
    __syncthreads();

    const int i = blockIdx.x * 256 + threadIdx.x;

    float xf[16];
    const float4* xv = reinterpret_cast<const float4*>(x + (size_t)i * CIN);
#pragma unroll
    for (int q = 0; q < 4; ++q)
        reinterpret_cast<float4*>(xf)[q] = xv[q];

    float y[16];
#pragma unroll
    for (int g = 0; g < 16; ++g) y[g] = 0.f;
#pragma unroll
    for (int f = 0; f < 16; ++f)
#pragma unroll
        for (int g = 0; g < 16; ++g)
            y[g] += xf[f] * sW[f * 16 + g];

#pragma unroll
    for (int g2 = 0; g2 < 8; ++g2)
        g_xwT[(n * 8 + g2) * N_IN + i] =
            make_float2(0.25f * y[2 * g2], 0.25f * y[2 * g2 + 1]);
}

// ---------------------------------------------------------------------------
// Main kernel: block owns 32 output rows (8 warps x 4 rows), loops over all
// 4 ensemble members and 8 K-slabs. Lanes split K (coalesced A stream);
// xw slab in SMEM as 8 planes [g2][KS] float2 (conflict-free LDS.64).
// Accumulators live in registers, warp-reduced at the end; lane 0 writes.
// ---------------------------------------------------------------------------
extern __shared__ float2 s_xw[];   // 8 * KS float2 = 128 KB

__global__ __launch_bounds__(256, 1)
void mfgl_main(const float* __restrict__ A,
               const float* __restrict__ bs,
               float* __restrict__ out) {
    const int tid  = threadIdx.x;
    const int lane = tid & 31;
    const int wid  = tid >> 5;
    const int row_base = blockIdx.x * 32 + wid * 4;

    float2 acc[4][8];
#pragma unroll
    for (int r = 0; r < 4; ++r)
#pragma unroll
        for (int g = 0; g < 8; ++g)
            acc[r][g] = make_float2(0.f, 0.f);

    for (int n = 0; n < N_ENS; ++n) {
        const float2* __restrict__ xw_n = g_xwT + (size_t)n * 8 * N_IN;

        for (int s = 0; s < NSLAB; ++s) {
            __syncthreads();  // previous slab fully consumed
            const int k0 = s * KS;
            // Cooperative slab load: 8*KS float2, coalesced within each plane.
#pragma unroll 8
            for (int j = tid; j < 8 * KS; j += 256) {
                const int g2 = j >> 11;          // j / KS  (KS = 2048)
                const int il = j & (KS - 1);
                s_xw[j] = xw_n[g2 * N_IN + k0 + il];
            }
            __syncthreads();

            const size_t base = ((size_t)(n * N_OUT + row_base)) * N_IN + k0 + lane;
            const float* __restrict__ a0 = A + base;
            const float* __restrict__ a1 = a0 + N_IN;
            const float* __restrict__ a2 = a1 + N_IN;
            const float* __restrict__ a3 = a2 + N_IN;

#pragma unroll 4
            for (int t = 0; t < KS / 32; ++t) {
                const int o = t * 32;
                const float v0 = a0[o];
                const float v1 = a1[o];
                const float v2 = a2[o];
                const float v3 = a3[o];
                const float2 p0 = make_float2(v0, v0);
                const float2 p1 = make_float2(v1, v1);
                const float2 p2 = make_float2(v2, v2);
                const float2 p3 = make_float2(v3, v3);
                const float2* __restrict__ xr = s_xw + o + lane;
#pragma unroll
                for (int g2 = 0; g2 < 8; ++g2) {
                    const float2 w = xr[g2 * KS];
                    acc[0][g2] = ffma2(p0, w, acc[0][g2]);
                    acc[1][g2] = ffma2(p1, w, acc[1][g2]);
                    acc[2][g2] = ffma2(p2, w, acc[2][g2]);
                    acc[3][g2] = ffma2(p3, w, acc[3][g2]);
                }
            }
        }
    }

    // Warp-level reduction across the K split (butterfly; all lanes end equal).
#pragma unroll
    for (int r = 0; r < 4; ++r)
#pragma unroll
        for (int g = 0; g < 8; ++g) {
            float xx = acc[r][g].x;
            float yy = acc[r][g].y;
#pragma unroll
            for (int off = 16; off > 0; off >>= 1) {
                xx += __shfl_xor_sync(0xffffffffu, xx, off);
                yy += __shfl_xor_sync(0xffffffffu, yy, off);
            }
            acc[r][g] = make_float2(xx, yy);
        }

    if (lane == 0) {
        float2* out2 = reinterpret_cast<float2*>(out);
#pragma unroll
        for (int r = 0; r < 4; ++r) {
            const int o = row_base + r;
#pragma unroll
            for (int g2 = 0; g2 < 8; ++g2) {
                const int g = 2 * g2;
                const float bx = 0.25f * (bs[g]     + bs[16 + g]     +
                                          bs[32 + g]     + bs[48 + g]);
                const float by = 0.25f * (bs[g + 1] + bs[16 + g + 1] +
                                          bs[32 + g + 1] + bs[48 + g + 1]);
                out2[(size_t)o * 8 + g2] =
                    make_float2(acc[r][g2].x + bx, acc[r][g2].y + by);
            }
        }
    }
}

// ---------------------------------------------------------------------------
// Launch: inputs in metadata order: x, As, Ws, bs. Output fp32 [4096,16].
// ---------------------------------------------------------------------------
extern "C" void kernel_launch(void* const* d_in, const int* in_sizes, int n_in,
                              void* d_out, int out_size) {
    const float* x  = (const float*)d_in[0];
    const float* As = (const float*)d_in[1];
    const float* Ws = (const float*)d_in[2];
    const float* bs = (const float*)d_in[3];
    float* out = (float*)d_out;

    precompute_xw<<<dim3(N_IN / 256, N_ENS), 256>>>(x, Ws);

    const int smem_bytes = 8 * KS * (int)sizeof(float2);  // 131072
    cudaFuncSetAttribute(mfgl_main,
                         cudaFuncAttributeMaxDynamicSharedMemorySize,
                         smem_bytes);
    mfgl_main<<<MAIN_BLOCKS, 256, smem_bytes>>>(As, bs, out);
}

// round 8
// speedup vs baseline: 1.2946x; 1.2761x over previous
#include <cuda_runtime.h>
#include <cstdint>

// Problem constants
#define N_ENS  4
#define N_IN   16384
#define N_OUT  4096
#define CIN    16
#define COUT   16
#define KS     1024                  // K-slab staged in SMEM per buffer
#define NSLAB  (N_IN / KS)           // 16
#define SLABS_TOTAL (N_ENS * NSLAB)  // 64
#define THREADS 512                  // 16 warps, 2 rows/warp -> 32 rows/block
#define MAIN_BLOCKS (N_OUT / 32)     // 128

// Scratch: xw planes [n][g2][i] as float2 (pair over g). 4 MB.
// float4-typed for 16B alignment (cp.async 16B needs it).
__device__ float4 g_xwT4[(N_ENS * 8 * N_IN) / 2];

union F2U { float2 f; unsigned long long u; };

__device__ __forceinline__ float2 ffma2(float2 a, float2 b, float2 c) {
    F2U A, B, C, D;
    A.f = a; B.f = b; C.f = c;
    asm("fma.rn.f32x2 %0, %1, %2, %3;"
        : "=l"(D.u) : "l"(A.u), "l"(B.u), "l"(C.u));
    return D.f;
}

__device__ __forceinline__ uint32_t smem_u32(const void* p) {
    uint32_t a;
    asm("{ .reg .u64 t; cvta.to.shared.u64 t, %1; cvt.u32.u64 %0, t; }"
        : "=r"(a) : "l"(p));
    return a;
}

__device__ __forceinline__ void cp_async16(uint32_t saddr, const void* gptr) {
    asm volatile("cp.async.cg.shared.global [%0], [%1], 16;"
                 :: "r"(saddr), "l"(gptr));
}
__device__ __forceinline__ void cp_commit() {
    asm volatile("cp.async.commit_group;");
}

// ---------------------------------------------------------------------------
// Kernel 0: xw[n][i][g] = 0.25 * sum_f x[i][f] * W[n][f][g], stored as
// plane-major float2: g_xwT[(n*8+g2)*N_IN + i].
// ---------------------------------------------------------------------------
__global__ void precompute_xw(const float* __restrict__ x,
                              const float* __restrict__ Ws) {
    __shared__ float sW[CIN * COUT];
    const int n = blockIdx.y;
    sW[threadIdx.x] = Ws[n * (CIN * COUT) + threadIdx.x];
    __syncthreads();

    const int i = blockIdx.x * 256 + threadIdx.x;

    float xf[16];
    const float4* xv = reinterpret_cast<const float4*>(x + (size_t)i * CIN);
#pragma unroll
    for (int q = 0; q < 4; ++q)
        reinterpret_cast<float4*>(xf)[q] = xv[q];

    float y[16];
#pragma unroll
    for (int g = 0; g < 16; ++g) y[g] = 0.f;
#pragma unroll
    for (int f = 0; f < 16; ++f)
#pragma unroll
        for (int g = 0; g < 16; ++g)
            y[g] += xf[f] * sW[f * 16 + g];

    float2* xwT = reinterpret_cast<float2*>(g_xwT4);
#pragma unroll
    for (int g2 = 0; g2 < 8; ++g2)
        xwT[(size_t)(n * 8 + g2) * N_IN + i] =
            make_float2(0.25f * y[2 * g2], 0.25f * y[2 * g2 + 1]);
}

// ---------------------------------------------------------------------------
// Main kernel: 512 threads = 16 warps x 2 rows = 32 output rows per block.
// Lanes split K (coalesced A stream, k = lane mod 32); xw slab staged in
// double-buffered SMEM via cp.async (8 planes [g2][KS] float2, LDS.64
// conflict-free). 64 slab iterations (4 ensembles x 16 slabs).
// ---------------------------------------------------------------------------
extern __shared__ float2 s_xw[];   // 2 buffers x 8*KS float2 = 128 KB

__global__ __launch_bounds__(THREADS, 1)
void mfgl_main(const float* __restrict__ A,
               const float* __restrict__ bs,
               float* __restrict__ out) {
    const int tid  = threadIdx.x;
    const int lane = tid & 31;
    const int wid  = tid >> 5;
    const int row0 = blockIdx.x * 32 + wid * 2;

    const float2* __restrict__ xwT = reinterpret_cast<const float2*>(g_xwT4);
    const uint32_t sbase = smem_u32(s_xw);

    float2 acc[2][8];
#pragma unroll
    for (int r = 0; r < 2; ++r)
#pragma unroll
        for (int g = 0; g < 8; ++g)
            acc[r][g] = make_float2(0.f, 0.f);

    // ---- prefetch helper (inlined twice) ------------------------------
    // slab idx -> n = idx>>4, s = idx&15. Buffer holds 8 planes x KS float2
    // = 4096 16B chunks; 512 threads x 8 chunks each.
#define PREFETCH(IDX, BUF)                                                  \
    do {                                                                    \
        const int _n = (IDX) >> 4;                                          \
        const int _k0 = ((IDX) & 15) * KS;                                  \
        const float2* __restrict__ _xw = xwT + (size_t)_n * 8 * N_IN;       \
        const uint32_t _dst = sbase + (BUF) * 65536u + (uint32_t)tid * 16u; \
        _Pragma("unroll")                                                   \
        for (int _i = 0; _i < 8; ++_i) {                                    \
            const int _c  = tid + _i * THREADS;                             \
            const int _g2 = _c >> 9;            /* 512 chunks per plane */  \
            const int _kk = (_c & 511) << 1;                                \
            cp_async16(_dst + (uint32_t)_i * (THREADS * 16u),               \
                       _xw + (size_t)_g2 * N_IN + _k0 + _kk);               \
        }                                                                   \
        cp_commit();                                                        \
    } while (0)

    PREFETCH(0, 0);

    for (int idx = 0; idx < SLABS_TOTAL; ++idx) {
        if (idx + 1 < SLABS_TOTAL) {
            PREFETCH(idx + 1, (idx + 1) & 1);
            asm volatile("cp.async.wait_group 1;");   // slab idx complete
        } else {
            asm volatile("cp.async.wait_group 0;");
        }
        __syncthreads();   // make all threads' cp.async data visible

        const int n  = idx >> 4;
        const int k0 = (idx & 15) * KS;
        const float2* __restrict__ sx = s_xw + (idx & 1) * (8 * KS);

        const size_t base =
            ((size_t)(n * N_OUT + row0)) * N_IN + k0 + lane;
        const float* __restrict__ a0 = A + base;
        const float* __restrict__ a1 = a0 + N_IN;

#pragma unroll 4
        for (int t = 0; t < KS / 32; ++t) {
            const int o = t * 32;
            const float v0 = a0[o];
            const float v1 = a1[o];
            const float2 p0 = make_float2(v0, v0);
            const float2 p1 = make_float2(v1, v1);
            const float2* __restrict__ xr = sx + o + lane;
#pragma unroll
            for (int g2 = 0; g2 < 8; ++g2) {
                const float2 w = xr[g2 * KS];
                acc[0][g2] = ffma2(p0, w, acc[0][g2]);
                acc[1][g2] = ffma2(p1, w, acc[1][g2]);
            }
        }
        __syncthreads();   // WAR: buffer (idx&1) may be overwritten next+1
    }

    // Warp-level butterfly reduction across the K split.
#pragma unroll
    for (int r = 0; r < 2; ++r)
#pragma unroll
        for (int g = 0; g < 8; ++g) {
            float xx = acc[r][g].x;
            float yy = acc[r][g].y;
#pragma unroll
            for (int off = 16; off > 0; off >>= 1) {
                xx += __shfl_xor_sync(0xffffffffu, xx, off);
                yy += __shfl_xor_sync(0xffffffffu, yy, off);
            }
            acc[r][g] = make_float2(xx, yy);
        }

    if (lane == 0) {
        float2* out2 = reinterpret_cast<float2*>(out);
#pragma unroll
        for (int r = 0; r < 2; ++r) {
            const int o = row0 + r;
#pragma unroll
            for (int g2 = 0; g2 < 8; ++g2) {
                const int g = 2 * g2;
                const float bx = 0.25f * (bs[g]     + bs[16 + g] +
                                          bs[32 + g] + bs[48 + g]);
                const float by = 0.25f * (bs[g + 1] + bs[16 + g + 1] +
                                          bs[32 + g + 1] + bs[48 + g + 1]);
                out2[(size_t)o * 8 + g2] =
                    make_float2(acc[r][g2].x + bx, acc[r][g2].y + by);
            }
        }
    }
}

// ---------------------------------------------------------------------------
// Launch: inputs in metadata order: x, As, Ws, bs. Output fp32 [4096,16].
// ---------------------------------------------------------------------------
extern "C" void kernel_launch(void* const* d_in, const int* in_sizes, int n_in,
                              void* d_out, int out_size) {
    const float* x  = (const float*)d_in[0];
    const float* As = (const float*)d_in[1];
    const float* Ws = (const float*)d_in[2];
    const float* bs = (const float*)d_in[3];
    float* out = (float*)d_out;

    precompute_xw<<<dim3(N_IN / 256, N_ENS), 256>>>(x, Ws);

    const int smem_bytes = 2 * 8 * KS * (int)sizeof(float2);  // 131072
    cudaFuncSetAttribute(mfgl_main,
                         cudaFuncAttributeMaxDynamicSharedMemorySize,
                         smem_bytes);
    mfgl_main<<<MAIN_BLOCKS, THREADS, smem_bytes>>>(As, bs, out);
}

// round 9
// speedup vs baseline: 2.0992x; 1.6216x over previous
#include <cuda_runtime.h>
#include <cstdint>

// Problem constants
#define N_ENS  4
#define N_IN   16384
#define N_OUT  4096
#define CIN    16
#define COUT   16
#define KS     1024                  // K-slab (floats) staged in SMEM per buffer
#define NSLAB  (N_IN / KS)           // 16
#define SLABS_TOTAL (N_ENS * NSLAB)  // 64
#define THREADS 256                  // 8 warps x 4 rows = 32 rows/block
#define MAIN_BLOCKS (N_OUT / 32)     // 128
#define TPB  (KS / 256)              // 4 blocks of 4 big-iters per slab
#define NBLK_TOTAL (SLABS_TOTAL * 4) // 256 pipeline blocks

// Scratch: xw planes [n][g2][i] as float2 (pair over g). 4 MB, 16B-aligned.
__device__ float4 g_xwT4[(N_ENS * 8 * N_IN) / 2];

union F2U { float2 f; unsigned long long u; };

__device__ __forceinline__ float2 ffma2(float2 a, float2 b, float2 c) {
    F2U A, B, C, D;
    A.f = a; B.f = b; C.f = c;
    asm("fma.rn.f32x2 %0, %1, %2, %3;"
        : "=l"(D.u) : "l"(A.u), "l"(B.u), "l"(C.u));
    return D.f;
}

__device__ __forceinline__ uint32_t smem_u32(const void* p) {
    uint32_t a;
    asm("{ .reg .u64 t; cvta.to.shared.u64 t, %1; cvt.u32.u64 %0, t; }"
        : "=r"(a) : "l"(p));
    return a;
}

__device__ __forceinline__ void cp_async16(uint32_t saddr, const void* gptr) {
    asm volatile("cp.async.cg.shared.global [%0], [%1], 16;"
                 :: "r"(saddr), "l"(gptr));
}
__device__ __forceinline__ void cp_commit() {
    asm volatile("cp.async.commit_group;");
}

// ---------------------------------------------------------------------------
// Kernel 0: xw[n][i][g] = 0.25 * sum_f x[i][f] * W[n][f][g], plane-major
// float2: g_xwT[(n*8+g2)*N_IN + i].
// ---------------------------------------------------------------------------
__global__ void precompute_xw(const float* __restrict__ x,
                              const float* __restrict__ Ws) {
    __shared__ float sW[CIN * COUT];
    const int n = blockIdx.y;
    sW[threadIdx.x] = Ws[n * (CIN * COUT) + threadIdx.x];
    __syncthreads();

    const int i = blockIdx.x * 256 + threadIdx.x;

    float xf[16];
    const float4* xv = reinterpret_cast<const float4*>(x + (size_t)i * CIN);
#pragma unroll
    for (int q = 0; q < 4; ++q)
        reinterpret_cast<float4*>(xf)[q] = xv[q];

    float y[16];
#pragma unroll
    for (int g = 0; g < 16; ++g) y[g] = 0.f;
#pragma unroll
    for (int f = 0; f < 16; ++f)
#pragma unroll
        for (int g = 0; g < 16; ++g)
            y[g] += xf[f] * sW[f * 16 + g];

    float2* xwT = reinterpret_cast<float2*>(g_xwT4);
#pragma unroll
    for (int g2 = 0; g2 < 8; ++g2)
        xwT[(size_t)(n * 8 + g2) * N_IN + i] =
            make_float2(0.25f * y[2 * g2], 0.25f * y[2 * g2 + 1]);
}

// ---------------------------------------------------------------------------
// Main kernel. 8 warps x 4 rows/warp = 32 rows/block.
// Lane L owns k = {2L, 2L+1} within a 64-k big-iteration:
//   A: per row one LDG.64 (float2), perfectly coalesced 256 B/warp.
//   w: per g2 one LDS.128 at offset L*16 -> conflict-free, gives the two
//      k's (g-pair) float2s.
// A stream is software-pipelined one 4-iteration block (256 k) ahead in
// registers; xw slabs are cp.async double-buffered in SMEM.
// ---------------------------------------------------------------------------
extern __shared__ float2 s_xw[];   // 2 buffers x 8*KS float2 = 128 KB

__global__ __launch_bounds__(THREADS, 1)
void mfgl_main(const float* __restrict__ A,
               const float* __restrict__ bs,
               float* __restrict__ out) {
    const int tid  = threadIdx.x;
    const int lane = tid & 31;
    const int wid  = tid >> 5;
    const int row0 = blockIdx.x * 32 + wid * 4;

    const float2* __restrict__ xwT = reinterpret_cast<const float2*>(g_xwT4);
    const uint32_t sbase = smem_u32(s_xw);

    float2 acc[4][8];
#pragma unroll
    for (int r = 0; r < 4; ++r)
#pragma unroll
        for (int g = 0; g < 8; ++g)
            acc[r][g] = make_float2(0.f, 0.f);

    // A base address of pipeline block bl (bl in [0, 256)):
    //   idx = bl>>2 (slab), tb = bl&3 (block in slab), covers k-range of 256.
    auto a_base = [&](int bl) -> const float2* {
        const int idx = bl >> 2;
        const int n   = idx >> 4;
        const int k0  = (idx & 15) * KS + (bl & 3) * 256;
        return reinterpret_cast<const float2*>(
            A + ((size_t)(n * N_OUT + row0)) * N_IN + k0) + lane;
    };

    // cp.async one xw slab into buffer BUF. 64 KB = 4096 x 16B chunks.
#define PREFETCH_XW(IDX, BUF)                                               \
    do {                                                                    \
        const int _n = (IDX) >> 4;                                          \
        const int _k0 = ((IDX) & 15) * KS;                                  \
        const float2* __restrict__ _xw = xwT + (size_t)_n * 8 * N_IN;       \
        const uint32_t _dst = sbase + (BUF) * 65536u + (uint32_t)tid * 16u; \
        _Pragma("unroll")                                                   \
        for (int _i = 0; _i < 16; ++_i) {                                   \
            const int _c  = tid + _i * THREADS;                             \
            const int _g2 = _c >> 9;            /* 512 chunks per plane */  \
            const int _kk = (_c & 511) << 1;                                \
            cp_async16(_dst + (uint32_t)_i * (THREADS * 16u),               \
                       _xw + (size_t)_g2 * N_IN + _k0 + _kk);               \
        }                                                                   \
        cp_commit();                                                        \
    } while (0)

    PREFETCH_XW(0, 0);

    // Prime A register pipeline with block 0.
    float2 cur[4][4];
    {
        const float2* pb = a_base(0);
#pragma unroll
        for (int r = 0; r < 4; ++r)
#pragma unroll
            for (int ts = 0; ts < 4; ++ts)
                cur[r][ts] = pb[(size_t)r * (N_IN / 2) + ts * 32];
    }

    for (int idx = 0; idx < SLABS_TOTAL; ++idx) {
        if (idx + 1 < SLABS_TOTAL) {
            PREFETCH_XW(idx + 1, (idx + 1) & 1);
            asm volatile("cp.async.wait_group 1;");   // slab idx complete
        } else {
            asm volatile("cp.async.wait_group 0;");
        }
        __syncthreads();

        const float2* __restrict__ sx = s_xw + (idx & 1) * (8 * KS);

#pragma unroll
        for (int tb = 0; tb < 4; ++tb) {
            // --- prefetch next 256-k block of A into registers ---------
            float2 nxt[4][4];
            {
                int bln = idx * 4 + tb + 1;
                if (bln >= NBLK_TOTAL) bln = 0;   // dead load, in-bounds
                const float2* pb = a_base(bln);
#pragma unroll
                for (int r = 0; r < 4; ++r)
#pragma unroll
                    for (int ts = 0; ts < 4; ++ts)
                        nxt[r][ts] = pb[(size_t)r * (N_IN / 2) + ts * 32];
            }

            // --- compute current block (4 big-iters x 64 k) ------------
#pragma unroll
            for (int ts = 0; ts < 4; ++ts) {
                const int off = (tb * 4 + ts) * 64 + 2 * lane;  // float2 idx
                const float2 a0 = cur[0][ts];
                const float2 a1 = cur[1][ts];
                const float2 a2 = cur[2][ts];
                const float2 a3 = cur[3][ts];
                const float2 p0x = make_float2(a0.x, a0.x);
                const float2 p0y = make_float2(a0.y, a0.y);
                const float2 p1x = make_float2(a1.x, a1.x);
                const float2 p1y = make_float2(a1.y, a1.y);
                const float2 p2x = make_float2(a2.x, a2.x);
                const float2 p2y = make_float2(a2.y, a2.y);
                const float2 p3x = make_float2(a3.x, a3.x);
                const float2 p3y = make_float2(a3.y, a3.y);
#pragma unroll
                for (int g2 = 0; g2 < 8; ++g2) {
                    const float4 wv = *reinterpret_cast<const float4*>(
                        sx + (size_t)g2 * KS + off);
                    const float2 wk0 = make_float2(wv.x, wv.y);
                    const float2 wk1 = make_float2(wv.z, wv.w);
                    acc[0][g2] = ffma2(p0x, wk0, acc[0][g2]);
                    acc[0][g2] = ffma2(p0y, wk1, acc[0][g2]);
                    acc[1][g2] = ffma2(p1x, wk0, acc[1][g2]);
                    acc[1][g2] = ffma2(p1y, wk1, acc[1][g2]);
                    acc[2][g2] = ffma2(p2x, wk0, acc[2][g2]);
                    acc[2][g2] = ffma2(p2y, wk1, acc[2][g2]);
                    acc[3][g2] = ffma2(p3x, wk0, acc[3][g2]);
                    acc[3][g2] = ffma2(p3y, wk1, acc[3][g2]);
                }
            }

#pragma unroll
            for (int r = 0; r < 4; ++r)
#pragma unroll
                for (int ts = 0; ts < 4; ++ts)
                    cur[r][ts] = nxt[r][ts];
        }
        __syncthreads();   // WAR on smem buffer (idx & 1)
    }

    // Warp-level butterfly reduction across the K split.
#pragma unroll
    for (int r = 0; r < 4; ++r)
#pragma unroll
        for (int g = 0; g < 8; ++g) {
            float xx = acc[r][g].x;
            float yy = acc[r][g].y;
#pragma unroll
            for (int off = 16; off > 0; off >>= 1) {
                xx += __shfl_xor_sync(0xffffffffu, xx, off);
                yy += __shfl_xor_sync(0xffffffffu, yy, off);
            }
            acc[r][g] = make_float2(xx, yy);
        }

    if (lane == 0) {
        float2* out2 = reinterpret_cast<float2*>(out);
#pragma unroll
        for (int r = 0; r < 4; ++r) {
            const int o = row0 + r;
#pragma unroll
            for (int g2 = 0; g2 < 8; ++g2) {
                const int g = 2 * g2;
                const float bx = 0.25f * (bs[g]     + bs[16 + g] +
                                          bs[32 + g] + bs[48 + g]);
                const float by = 0.25f * (bs[g + 1] + bs[16 + g + 1] +
                                          bs[32 + g + 1] + bs[48 + g + 1]);
                out2[(size_t)o * 8 + g2] =
                    make_float2(acc[r][g2].x + bx, acc[r][g2].y + by);
            }
        }
    }
}

// ---------------------------------------------------------------------------
// Launch: inputs in metadata order: x, As, Ws, bs. Output fp32 [4096,16].
// ---------------------------------------------------------------------------
extern "C" void kernel_launch(void* const* d_in, const int* in_sizes, int n_in,
                              void* d_out, int out_size) {
    const float* x  = (const float*)d_in[0];
    const float* As = (const float*)d_in[1];
    const float* Ws = (const float*)d_in[2];
    const float* bs = (const float*)d_in[3];
    float* out = (float*)d_out;

    precompute_xw<<<dim3(N_IN / 256, N_ENS), 256>>>(x, Ws);

    const int smem_bytes = 2 * 8 * KS * (int)sizeof(float2);  // 131072
    cudaFuncSetAttribute(mfgl_main,
                         cudaFuncAttributeMaxDynamicSharedMemorySize,
                         smem_bytes);
    mfgl_main<<<MAIN_BLOCKS, THREADS, smem_bytes>>>(As, bs, out);
}